// round 6
// baseline (speedup 1.0000x reference)
#include <cuda_runtime.h>

// AELoss: pred/target (64,4,256,256) fp32, match (64,128,2,2) int32.
// out[0] = 0.25 * sum_b pull_b, out[1] = 0.25 * sum_b push_b
//
// pull_b = sum_{n,c} (tl-br)^2 / 2 / N        (since tl-me = (tl-br)/2)
// push_b = sum_{i!=j} relu(1 - |s_i - s_j|) / (N*(N-1)),  s_i = sum_c (tl+br)/2
//
// 256 threads/CTA: threads 0..127 gather keypoints; all 256 split the push
// j-range (2 threads per keypoint, 64 js each). Per-warp shuffle reduce, then
// lane-0 fire-and-forget RED.ADD straight into out[] (zeroed by a memset node).

#define B_IMGS 64
#define N_KP   128
#define C_CH   4
#define HW     65536   // 256*256
#define W_DIM  256
#define TPB    256

__global__ __launch_bounds__(TPB, 1)
void ae_kernel(const float* __restrict__ pred,
               const float* __restrict__ target,
               const int*   __restrict__ match,
               float*       __restrict__ out) {
    const int b = blockIdx.x;
    const int t = threadIdx.x;

    __shared__ float s_me[N_KP];

    float pull = 0.0f;

    if (t < N_KP) {
        // match[b, t, {tl,br}, {y,x}] -- one int4 per (b,kp)
        const int4 m = __ldg(reinterpret_cast<const int4*>(match) + b * N_KP + t);
        const int tl_off = m.x * W_DIM + m.y;
        const int br_off = m.z * W_DIM + m.w;

        const float* __restrict__ p = pred   + (size_t)b * C_CH * HW;
        const float* __restrict__ tg = target + (size_t)b * C_CH * HW;

        float s = 0.0f;
        #pragma unroll
        for (int c = 0; c < C_CH; ++c) {
            const float tl = __ldg(p  + c * HW + tl_off);
            const float br = __ldg(tg + c * HW + br_off);
            const float d = tl - br;
            pull += 0.5f * d * d;
            s    += 0.5f * (tl + br);
        }
        s_me[t] = s;
    }
    __syncthreads();

    // push: thread t covers keypoint i = t&127, j in [h*64, h*64+64), h = t>>7
    const int i = t & (N_KP - 1);
    const int h = t >> 7;
    const float s = s_me[i];

    float push = (h == (i >> 6)) ? -1.0f : 0.0f;   // remove j==i self term (==1)
    const float4* __restrict__ s4 =
        reinterpret_cast<const float4*>(s_me + h * (N_KP / 2));
    #pragma unroll
    for (int j = 0; j < N_KP / 8; ++j) {           // 16 float4 = 64 js
        const float4 v = s4[j];
        push += fmaxf(0.0f, 1.0f - fabsf(s - v.x));
        push += fmaxf(0.0f, 1.0f - fabsf(s - v.y));
        push += fmaxf(0.0f, 1.0f - fabsf(s - v.z));
        push += fmaxf(0.0f, 1.0f - fabsf(s - v.w));
    }

    // warp-level reduce, then lane 0 RED.ADDs directly to out[] (no smem stage)
    #pragma unroll
    for (int off = 16; off > 0; off >>= 1) {
        pull += __shfl_down_sync(0xFFFFFFFFu, pull, off);
        push += __shfl_down_sync(0xFFFFFFFFu, push, off);
    }
    if ((t & 31) == 0) {
        if (t < N_KP)   // warps 4..7 carry no pull contribution
            atomicAdd(&out[0], pull * (0.25f / (float)N_KP));
        atomicAdd(&out[1], push * (0.25f / (float)(N_KP * (N_KP - 1))));
    }
}

extern "C" void kernel_launch(void* const* d_in, const int* in_sizes, int n_in,
                              void* d_out, int out_size) {
    const float* pred   = (const float*)d_in[0];
    const float* target = (const float*)d_in[1];
    const int*   match  = (const int*)d_in[2];
    float* out = (float*)d_out;

    cudaMemsetAsync(out, 0, 2 * sizeof(float));
    ae_kernel<<<B_IMGS, TPB>>>(pred, target, match, out);
}